// round 8
// baseline (speedup 1.0000x reference)
#include <cuda_runtime.h>
#include <cstdint>

// Householder reflection per row, B=8192, L=4096, fp32.
//   out[b,:] = z[b,:] - 2 * v[b,:] * (v.z)/(v.v)
//
// R7 base (61.9us, DRAM 83%): TMA bulk loads into smem, register-resident
// single smem pass, per-thread __stcs stores.
// R8 change: 2 consecutive rows per CTA (grid=4096). The v row-pair is one
// contiguous 32KB cp.async.bulk, likewise z. Bigger DRAM bursts + better
// page locality, half the per-row mbarrier/init overhead. Rows processed
// back-to-back from a single barrier; 3 CTAs/SM keep ~192KB in flight.

constexpr int THREADS = 256;
constexpr int L       = 4096;
constexpr int L4      = L / 4;               // 1024 float4 per row
constexpr int PER     = L4 / THREADS;        // 4 float4 per thread per tensor
constexpr int ROWS_PER_CTA = 2;
constexpr int PAIR_BYTES   = ROWS_PER_CTA * L * 4;      // 32768 per tensor
constexpr int SMEM_BYTES   = 2 * PAIR_BYTES;            // 65536 (v pair + z pair)

__device__ __forceinline__ uint32_t smem_u32(const void* p) {
    return (uint32_t)__cvta_generic_to_shared(p);
}

__global__ __launch_bounds__(THREADS)
void hh_tma_r8_kernel(const float4* __restrict__ v,
                      const float4* __restrict__ z,
                      float4* __restrict__ out)
{
    extern __shared__ float4 sm[];   // v rows: [0, 2048), z rows: [2048, 4096)
    __shared__ __align__(8) unsigned long long mbar;
    __shared__ float s_part[16];     // 8 warps x {vz, vv}
    __shared__ float s_scale;

    const int t    = threadIdx.x;
    const int lane = t & 31;
    const int wid  = t >> 5;
    const size_t pair_base = (size_t)blockIdx.x * (ROWS_PER_CTA * L4);

    const uint32_t mb = smem_u32(&mbar);

    if (t == 0) {
        asm volatile("mbarrier.init.shared::cta.b64 [%0], %1;"
                     :: "r"(mb), "r"(1));
        asm volatile("fence.proxy.async.shared::cta;" ::: "memory");
    }
    __syncthreads();

    if (t == 0) {
        asm volatile("mbarrier.arrive.expect_tx.shared::cta.b64 _, [%0], %1;"
                     :: "r"(mb), "r"(2 * PAIR_BYTES) : "memory");
        asm volatile("cp.async.bulk.shared::cta.global.mbarrier::complete_tx::bytes"
                     " [%0], [%1], %2, [%3];"
                     :: "r"(smem_u32(sm)), "l"(v + pair_base),
                        "r"(PAIR_BYTES), "r"(mb) : "memory");
        asm volatile("cp.async.bulk.shared::cta.global.mbarrier::complete_tx::bytes"
                     " [%0], [%1], %2, [%3];"
                     :: "r"(smem_u32(sm + 2 * L4)), "l"(z + pair_base),
                        "r"(PAIR_BYTES), "r"(mb) : "memory");
    }

    // Wait (parity 0, single-shot), acquire for generic smem reads
    {
        uint32_t done;
        asm volatile(
            "{\n\t.reg .pred p;\n\t"
            "mbarrier.try_wait.parity.acquire.cta.shared::cta.b64 p, [%1], %2;\n\t"
            "selp.b32 %0, 1, 0, p;\n\t}"
            : "=r"(done) : "r"(mb), "r"(0) : "memory");
        while (!done) {
            asm volatile(
                "{\n\t.reg .pred p;\n\t"
                "mbarrier.try_wait.parity.acquire.cta.shared::cta.b64 p, [%1], %2, 0x989680;\n\t"
                "selp.b32 %0, 1, 0, p;\n\t}"
                : "=r"(done) : "r"(mb), "r"(0) : "memory");
        }
    }

    #pragma unroll
    for (int r = 0; r < ROWS_PER_CTA; r++) {
        const float4* vs = sm + (size_t)r * L4;
        const float4* zs = sm + 2 * L4 + (size_t)r * L4;

        // Single smem pass: payload into registers, both dots accumulated
        float4 rv[PER], rz[PER];
        float dvz = 0.0f, dvv = 0.0f;
        #pragma unroll
        for (int i = 0; i < PER; i++) {
            rv[i] = vs[t + i * THREADS];
            rz[i] = zs[t + i * THREADS];
            dvz += rv[i].x * rz[i].x + rv[i].y * rz[i].y
                 + rv[i].z * rz[i].z + rv[i].w * rz[i].w;
            dvv += rv[i].x * rv[i].x + rv[i].y * rv[i].y
                 + rv[i].z * rv[i].z + rv[i].w * rv[i].w;
        }

        #pragma unroll
        for (int off = 16; off > 0; off >>= 1) {
            dvz += __shfl_xor_sync(0xFFFFFFFFu, dvz, off);
            dvv += __shfl_xor_sync(0xFFFFFFFFu, dvv, off);
        }
        if (lane == 0) { s_part[wid] = dvz; s_part[8 + wid] = dvv; }
        __syncthreads();

        if (wid == 0) {
            float a = (lane < 8) ? s_part[lane] : 0.0f;
            float c = (lane < 8) ? s_part[8 + lane] : 0.0f;
            #pragma unroll
            for (int off = 4; off > 0; off >>= 1) {
                a += __shfl_xor_sync(0xFFFFFFFFu, a, off);
                c += __shfl_xor_sync(0xFFFFFFFFu, c, off);
            }
            if (lane == 0) s_scale = 2.0f * a / c;
        }
        __syncthreads();

        const float nscale = -s_scale;
        float4* og = out + pair_base + (size_t)r * L4;

        #pragma unroll
        for (int i = 0; i < PER; i++) {
            float4 o;
            o.x = fmaf(nscale, rv[i].x, rz[i].x);
            o.y = fmaf(nscale, rv[i].y, rz[i].y);
            o.z = fmaf(nscale, rv[i].z, rz[i].z);
            o.w = fmaf(nscale, rv[i].w, rz[i].w);
            __stcs(og + t + i * THREADS, o);
        }
    }
}

extern "C" void kernel_launch(void* const* d_in, const int* in_sizes, int n_in,
                              void* d_out, int out_size)
{
    const float4* v = (const float4*)d_in[0];
    const float4* z = (const float4*)d_in[1];
    float4* out = (float4*)d_out;

    const int B = in_sizes[0] / L;    // 8192

    static bool attr_set = false;
    if (!attr_set) {
        cudaFuncSetAttribute(hh_tma_r8_kernel,
                             cudaFuncAttributeMaxDynamicSharedMemorySize,
                             SMEM_BYTES);
        attr_set = true;
    }

    hh_tma_r8_kernel<<<B / ROWS_PER_CTA, THREADS, SMEM_BYTES>>>(v, z, out);
}